// round 14
// baseline (speedup 1.0000x reference)
#include <cuda_runtime.h>
#include <cstdint>
#include <cstddef>

// Problem constants
#define Bv   128
#define Tv   512
#define Vv   32000
#define Ev   256
#define Hv   128
#define G4H  512      // 4*H (gate columns per direction)
#define NW   1024     // 4H * 2 directions (concat fw|bw)

// Scratch: embW = emb @ [W_fw | W_bw] + [b_fw | b_bw]   (131 MB, device global)
__device__ float g_embW[(size_t)Vv * NW];

// ---------------------------------------------------------------------------
// f32x2 packed-math helpers (sm_103a; ptxas never emits FFMA2 from C++)
// ---------------------------------------------------------------------------
__device__ __forceinline__ unsigned long long fma2(unsigned long long a,
                                                   unsigned long long b,
                                                   unsigned long long c) {
    unsigned long long d;
    asm("fma.rn.f32x2 %0, %1, %2, %3;" : "=l"(d) : "l"(a), "l"(b), "l"(c));
    return d;
}
__device__ __forceinline__ unsigned long long dup2(float x) {
    unsigned long long d;
    asm("mov.b64 %0, {%1, %1};" : "=l"(d) : "f"(x));
    return d;
}
__device__ __forceinline__ unsigned long long pack2(float lo, float hi) {
    unsigned long long d;
    asm("mov.b64 %0, {%1, %2};" : "=l"(d) : "f"(lo), "f"(hi));
    return d;
}
__device__ __forceinline__ void unpack2(unsigned long long v, float& lo, float& hi) {
    asm("mov.b64 {%0, %1}, %2;" : "=f"(lo), "=f"(hi) : "l"(v));
}
__device__ __forceinline__ float lanesum(unsigned long long v) {
    float lo, hi; unpack2(v, lo, hi); return lo + hi;
}

// MUFU-direct activations (no divides, ~2-ulp accurate)
__device__ __forceinline__ float ex2f(float x) {
    float y; asm("ex2.approx.f32 %0, %1;" : "=f"(y) : "f"(x)); return y;
}
__device__ __forceinline__ float rcpf(float x) {
    float y; asm("rcp.approx.f32 %0, %1;" : "=f"(y) : "f"(x)); return y;
}
#define LOG2E 1.4426950408889634f
__device__ __forceinline__ float sigmoid_f(float x) {
    return rcpf(1.0f + ex2f(-LOG2E * x));          // 1/(1+e^-x)
}
__device__ __forceinline__ float tanh_f(float x) {
    return fmaf(-2.0f, rcpf(1.0f + ex2f(2.0f * LOG2E * x)), 1.0f); // 1-2/(1+e^2x)
}

// ---------------------------------------------------------------------------
// Kernel 1: embW[v][n] = sum_k emb[v][k] * W[k][n] + bias[n]
// M=32000, K=256, N=1024. 128x128 tile, BK=8, 256 threads, 8x8 per thread.
// ---------------------------------------------------------------------------
__global__ __launch_bounds__(256) void embw_gemm_kernel(
    const float* __restrict__ emb,
    const float* __restrict__ Wfw, const float* __restrict__ Wbw,
    const float* __restrict__ bfw, const float* __restrict__ bbw)
{
    __shared__ float As[8][128];
    __shared__ float Bs[8][128];

    const int tid = threadIdx.x;
    const int m0 = blockIdx.x * 128;
    const int n0 = blockIdx.y * 128;

    const float* Wp;
    const float* bp;
    int nb;
    if (n0 < G4H) { Wp = Wfw; bp = bfw; nb = n0; }
    else          { Wp = Wbw; bp = bbw; nb = n0 - G4H; }

    const int ar = tid >> 1;
    const int ac = (tid & 1) * 4;
    const int br = tid >> 5;
    const int bc = (tid & 31) * 4;
    const int tx = tid & 15;
    const int ty = tid >> 4;

    unsigned long long acc[8][4];
#pragma unroll
    for (int i = 0; i < 8; i++)
#pragma unroll
        for (int j2 = 0; j2 < 4; j2++) acc[i][j2] = 0ull;

    float4 av = *(const float4*)&emb[(size_t)(m0 + ar) * Ev + ac];
    float4 bv = *(const float4*)&Wp[(size_t)br * G4H + nb + bc];

    for (int kt = 0; kt < Ev / 8; ++kt) {
        As[ac + 0][ar] = av.x; As[ac + 1][ar] = av.y;
        As[ac + 2][ar] = av.z; As[ac + 3][ar] = av.w;
        *(float4*)&Bs[br][bc] = bv;
        __syncthreads();
        if (kt + 1 < Ev / 8) {
            int k0 = (kt + 1) * 8;
            av = *(const float4*)&emb[(size_t)(m0 + ar) * Ev + k0 + ac];
            bv = *(const float4*)&Wp[(size_t)(k0 + br) * G4H + nb + bc];
        }
#pragma unroll
        for (int kk = 0; kk < 8; ++kk) {
            float a[8];
            *(float4*)&a[0] = *(const float4*)&As[kk][ty * 8];
            *(float4*)&a[4] = *(const float4*)&As[kk][ty * 8 + 4];
            ulonglong2 b0 = *(const ulonglong2*)&Bs[kk][tx * 8];
            ulonglong2 b1 = *(const ulonglong2*)&Bs[kk][tx * 8 + 4];
#pragma unroll
            for (int i = 0; i < 8; i++) {
                unsigned long long ad = dup2(a[i]);
                acc[i][0] = fma2(ad, b0.x, acc[i][0]);
                acc[i][1] = fma2(ad, b0.y, acc[i][1]);
                acc[i][2] = fma2(ad, b1.x, acc[i][2]);
                acc[i][3] = fma2(ad, b1.y, acc[i][3]);
            }
        }
        __syncthreads();
    }

    float bias[8];
    *(float4*)&bias[0] = *(const float4*)&bp[nb + tx * 8];
    *(float4*)&bias[4] = *(const float4*)&bp[nb + tx * 8 + 4];
#pragma unroll
    for (int i = 0; i < 8; i++) {
        int row = m0 + ty * 8 + i;
        float c[8];
#pragma unroll
        for (int j2 = 0; j2 < 4; j2++)
            unpack2(acc[i][j2], c[2 * j2], c[2 * j2 + 1]);
        float4 v0, v1;
        v0.x = c[0] + bias[0]; v0.y = c[1] + bias[1];
        v0.z = c[2] + bias[2]; v0.w = c[3] + bias[3];
        v1.x = c[4] + bias[4]; v1.y = c[5] + bias[5];
        v1.z = c[6] + bias[6]; v1.w = c[7] + bias[7];
        *(float4*)&g_embW[(size_t)row * NW + n0 + tx * 8]     = v0;
        *(float4*)&g_embW[(size_t)row * NW + n0 + tx * 8 + 4] = v1;
    }
}

// ---------------------------------------------------------------------------
// Kernel 2: persistent LSTM, k-split across 512 threads (16 warps).
// grid = 128 blocks (1/SM): blockIdx.x&1 = direction, >>1 = batch pair.
// Thread t: cs = t&255 -> cols {cs, cs+256}, both rows; half = t>>8 ->
// k in [half*64, half*64+64). U: 44 k-rows/half in regs (44 u64), 20 in smem.
// k-hi warps add xw + own prefetch; k-lo warps reduce partials + activations;
// k-lo threads 128..255 carry c and run the epilogue.
// ---------------------------------------------------------------------------
#define KREG  44                         // k-rows in regs per half
#define NQH   5                          // smem quads per half (20 rows)
// smem: Uq[10][512] float4 + hrow[2][128] + pbuf[128]f2 + pred[256]f4 + tokb
#define LSTM_SMEM_BYTES (2 * NQH * G4H * 16 + 256 * 4 + 128 * 8 + 256 * 16 + 1024 * 4)

__global__ __launch_bounds__(512, 1) void lstm_kernel(
    const void*  __restrict__ tokens,
    const float* __restrict__ Ufw,
    const float* __restrict__ Ubw,
    float* __restrict__ out)
{
    extern __shared__ float smem[];
    float4* Uq   = (float4*)smem;                       // [2*NQH][512]
    float*  hrow = (float*)(Uq + 2 * NQH * G4H);        // [2][128] planar
    float2* pbuf = (float2*)(hrow + 256);               // [128] (p_r0, p_r1)
    float4* pred = (float4*)(pbuf + 128);               // [256] k-hi partials
    int*    tokb = (int*)(pred + 256);                  // [2][512]
    __shared__ int s_cnt;

    const int t    = threadIdx.x;
    const int cs   = t & 255;
    const int half = t >> 8;                 // 0 = k-lo, 1 = k-hi (whole warps)
    const int kbase = half * 64;
    const int j0 = cs;
    const int j1 = cs + 256;
    const int dir = blockIdx.x & 1;
    const int b0  = (blockIdx.x >> 1) * 2;
    const float* U = dir ? Ubw : Ufw;

    // ---- inline tokens-dtype detection (first 8 KB, in-bounds either way) ----
    if (t == 0) s_cnt = 0;
    __syncthreads();
    {
        const unsigned int* w = (const unsigned int*)tokens;
        int local = 0;
        for (int i = t; i < 1024; i += 512)
            if (w[2 * i + 1] == 0u) local++;
        atomicAdd(&s_cnt, local);
    }
    __syncthreads();
    const int is64 = (s_cnt > 512);

    // ---- U k-pairs (rows kbase .. kbase+KREG-1) into registers ----
    unsigned long long Ur0[KREG / 2], Ur1[KREG / 2];
#pragma unroll
    for (int p = 0; p < KREG / 2; p++) {
        int k = kbase + 2 * p;
        Ur0[p] = pack2(U[k * G4H + j0], U[(k + 1) * G4H + j0]);
        Ur1[p] = pack2(U[k * G4H + j1], U[(k + 1) * G4H + j1]);
    }

    // ---- U rows kbase+KREG .. kbase+63 into smem quads ----
    // Uq[hh*NQH + q][col] = rows hh*64+KREG+4q .. +3
    for (int idx = t; idx < 2 * NQH * G4H; idx += 512) {
        int qq  = idx >> 9;            // 0..9
        int col = idx & 511;
        int hh  = qq / NQH;
        int q   = qq - hh * NQH;
        int k   = hh * 64 + KREG + 4 * q;
        float4 v;
        v.x = U[(k + 0) * G4H + col];
        v.y = U[(k + 1) * G4H + col];
        v.z = U[(k + 2) * G4H + col];
        v.w = U[(k + 3) * G4H + col];
        Uq[qq * G4H + col] = v;
    }

    // ---- tokens for rows b0, b0+1 ----
    for (int idx = t; idx < 2 * Tv; idx += 512) {
        int r  = idx >> 9;
        int tt = idx & (Tv - 1);
        int tok;
        if (is64) tok = (int)((const long long*)tokens)[(size_t)(b0 + r) * Tv + tt];
        else      tok =       ((const int*)tokens)      [(size_t)(b0 + r) * Tv + tt];
        tokb[idx] = tok;
    }
    if (t < 128) { hrow[t] = 0.0f; hrow[128 + t] = 0.0f; }
    __syncthreads();

    const int cbase = dir * G4H;
    const float* eb = g_embW;
    const int cell = t - 128;            // epilogue threads: t in [128,256)
    float c0 = 0.0f, c1 = 0.0f, hl0 = 0.0f, hl1 = 0.0f;

    // initial xw prefetch (k-hi threads own xw)
    float xw00 = 0.0f, xw01 = 0.0f, xw10 = 0.0f, xw11 = 0.0f;
    if (half) {
        int t0 = dir ? (Tv - 1) : 0;
        int tk0 = tokb[t0], tk1 = tokb[Tv + t0];
        xw00 = eb[(size_t)tk0 * NW + cbase + j0];
        xw01 = eb[(size_t)tk1 * NW + cbase + j0];
        xw10 = eb[(size_t)tk0 * NW + cbase + j1];
        xw11 = eb[(size_t)tk1 * NW + cbase + j1];
    }

    const ulonglong2* h0q = (const ulonglong2*)hrow + (kbase >> 2);
    const ulonglong2* h1q = (const ulonglong2*)(hrow + 128) + (kbase >> 2);
    const ulonglong2* Uqv = (const ulonglong2*)(Uq + half * NQH * G4H);

    for (int s = 0; s < Tv; ++s) {
        const int tc = dir ? (Tv - 1 - s) : s;

        // k-hi: prefetch next step's xw (in flight during the serial tail)
        float nx00 = 0.0f, nx01 = 0.0f, nx10 = 0.0f, nx11 = 0.0f;
        if (half && s + 1 < Tv) {
            int tn = dir ? (tc - 1) : (tc + 1);
            int a = tokb[tn], b = tokb[Tv + tn];
            nx00 = eb[(size_t)a * NW + cbase + j0];
            nx01 = eb[(size_t)b * NW + cbase + j0];
            nx10 = eb[(size_t)a * NW + cbase + j1];
            nx11 = eb[(size_t)b * NW + cbase + j1];
        }

        // partial accumulators, lanes = (even-k, odd-k) within this k-half
        unsigned long long a00 = half ? pack2(xw00, 0.0f) : 0ull;
        unsigned long long a01 = half ? pack2(xw01, 0.0f) : 0ull;
        unsigned long long a10 = half ? pack2(xw10, 0.0f) : 0ull;
        unsigned long long a11 = half ? pack2(xw11, 0.0f) : 0ull;

#pragma unroll
        for (int q = 0; q < KREG / 4; q++) {        // reg-U quads (11)
            ulonglong2 h0 = h0q[q];
            ulonglong2 h1 = h1q[q];
            a00 = fma2(h0.x, Ur0[2 * q],     a00);
            a00 = fma2(h0.y, Ur0[2 * q + 1], a00);
            a01 = fma2(h1.x, Ur0[2 * q],     a01);
            a01 = fma2(h1.y, Ur0[2 * q + 1], a01);
            a10 = fma2(h0.x, Ur1[2 * q],     a10);
            a10 = fma2(h0.y, Ur1[2 * q + 1], a10);
            a11 = fma2(h1.x, Ur1[2 * q],     a11);
            a11 = fma2(h1.y, Ur1[2 * q + 1], a11);
        }
#pragma unroll
        for (int q = 0; q < NQH; q++) {             // smem-U quads (5)
            ulonglong2 h0 = h0q[KREG / 4 + q];
            ulonglong2 h1 = h1q[KREG / 4 + q];
            ulonglong2 ua = Uqv[q * G4H + j0];
            ulonglong2 ub = Uqv[q * G4H + j1];
            a00 = fma2(h0.x, ua.x, a00);
            a00 = fma2(h0.y, ua.y, a00);
            a01 = fma2(h1.x, ua.x, a01);
            a01 = fma2(h1.y, ua.y, a01);
            a10 = fma2(h0.x, ub.x, a10);
            a10 = fma2(h0.y, ub.y, a10);
            a11 = fma2(h1.x, ub.x, a11);
            a11 = fma2(h1.y, ub.y, a11);
        }

        if (half) {
            // k-hi: lane-sum partials, hand off to k-lo
            float4 pr;
            pr.x = lanesum(a00); pr.y = lanesum(a01);
            pr.z = lanesum(a10); pr.w = lanesum(a11);
            pred[cs] = pr;
        }
        __syncthreads();                             // bar1: partials ready

        float f0 = 0.0f, f1 = 0.0f, o0 = 0.0f, o1 = 0.0f;
        if (!half) {
            float4 pr = pred[cs];
            float z00 = lanesum(a00) + pr.x;
            float z01 = lanesum(a01) + pr.y;
            float z10 = lanesum(a10) + pr.z;
            float z11 = lanesum(a11) + pr.w;
            if (t < 128) {
                // cols (t, t+256) = (i, g) of cell t
                float i0 = sigmoid_f(z00), i1 = sigmoid_f(z01);
                float g0 = tanh_f(z10),    g1 = tanh_f(z11);
                pbuf[t] = make_float2(i0 * g0, i1 * g1);
            } else {
                // cols (t, t+256) = (f, o) of cell t-128
                f0 = sigmoid_f(z00); f1 = sigmoid_f(z01);
                o0 = sigmoid_f(z10); o1 = sigmoid_f(z11);
            }
        }
        __syncthreads();                             // bar2: pbuf ready

        if (!half && t >= 128) {
            float2 p = pbuf[cell];
            c0 = fmaf(f0, c0, p.x);
            c1 = fmaf(f1, c1, p.y);
            hl0 = o0 * tanh_f(c0);
            hl1 = o1 * tanh_f(c1);
            hrow[cell]       = hl0;
            hrow[128 + cell] = hl1;
            out[((size_t)b0 * Tv + tc) * 256 + dir * 128 + cell]       = hl0;
            out[((size_t)(b0 + 1) * Tv + tc) * 256 + dir * 128 + cell] = hl1;
        }
        __syncthreads();                             // bar3: h ready
        xw00 = nx00; xw01 = nx01; xw10 = nx10; xw11 = nx11;
    }

    // final states: after out[B,T,2H]: h_fw, c_fw, h_bw, c_bw (each [B,H])
    if (!half && t >= 128) {
        size_t fin  = (size_t)Bv * Tv * 256;
        size_t hoff = fin + (size_t)(dir * 2) * (Bv * Hv);
        out[hoff + (size_t)b0 * Hv + cell]                 = hl0;
        out[hoff + (size_t)(b0 + 1) * Hv + cell]           = hl1;
        out[hoff + Bv * Hv + (size_t)b0 * Hv + cell]       = c0;
        out[hoff + Bv * Hv + (size_t)(b0 + 1) * Hv + cell] = c1;
    }
}

// ---------------------------------------------------------------------------
// Inputs (metadata order): tokens, emb, W_fw, U_fw, b_fw, W_bw, U_bw, b_bw
// Output: out[B,T,2H] fp32, then h_fw, c_fw, h_bw, c_bw (each [B,H])
// ---------------------------------------------------------------------------
extern "C" void kernel_launch(void* const* d_in, const int* in_sizes, int n_in,
                              void* d_out, int out_size)
{
    const void*  tokens = d_in[0];
    const float* emb = (const float*)d_in[1];
    const float* Wfw = (const float*)d_in[2];
    const float* Ufw = (const float*)d_in[3];
    const float* bfw = (const float*)d_in[4];
    const float* Wbw = (const float*)d_in[5];
    const float* Ubw = (const float*)d_in[6];
    const float* bbw = (const float*)d_in[7];
    float* out = (float*)d_out;

    (void)in_sizes; (void)n_in; (void)out_size;

    dim3 ggrid(Vv / 128, NW / 128);
    embw_gemm_kernel<<<ggrid, 256>>>(emb, Wfw, Wbw, bfw, bbw);

    cudaFuncSetAttribute(lstm_kernel,
                         cudaFuncAttributeMaxDynamicSharedMemorySize,
                         LSTM_SMEM_BYTES);
    lstm_kernel<<<128, 512, LSTM_SMEM_BYTES>>>(tokens, Ufw, Ubw, out);
}